// round 9
// baseline (speedup 1.0000x reference)
#include <cuda_runtime.h>
#include <stdint.h>

#define N_NODES   100000
#define N_EDGES   1600000
#define IN_FEATS  128
#define OUT_FEATS 256
#define K_TOP     32

// Scratch (no cudaMalloc allowed)
__device__ float g_xsparse[(size_t)N_NODES * IN_FEATS];   // 51.2 MB
__device__ float g_agg[(size_t)N_NODES * IN_FEATS];       // 51.2 MB

// ---------------------------------------------------------------------------
// K1: scatter top-k -> dense x_sparse[N,128]. atomicAdd (indices may repeat).
// ---------------------------------------------------------------------------
__global__ __launch_bounds__(256) void scatter_kernel(
    const float* __restrict__ vals, const int* __restrict__ idx)
{
    __shared__ float s[8][IN_FEATS];
    const int warp = threadIdx.x >> 5;
    const int lane = threadIdx.x & 31;
    const int node = blockIdx.x * 8 + warp;
    if (node >= N_NODES) return;

    ((float4*)s[warp])[lane] = make_float4(0.f, 0.f, 0.f, 0.f);
    __syncwarp();

    const float v = vals[(size_t)node * K_TOP + lane];
    const int   i = idx [(size_t)node * K_TOP + lane];
    atomicAdd(&s[warp][i], v);
    __syncwarp();

    ((float4*)(g_xsparse + (size_t)node * IN_FEATS))[lane] = ((float4*)s[warp])[lane];
}

// ---------------------------------------------------------------------------
// K2: SpMM (mean agg). Warp per node, binary search on sorted row[], 4-deep
// unrolled float4 gathers from L2-resident x_sparse for MLP.
// ---------------------------------------------------------------------------
__global__ __launch_bounds__(256) void spmm_kernel(
    const int* __restrict__ row, const int* __restrict__ col,
    const float* __restrict__ degrees)
{
    const int warp = threadIdx.x >> 5;
    const int lane = threadIdx.x & 31;
    const int node = blockIdx.x * 8 + warp;
    if (node >= N_NODES) return;

    int lo = 0, hi = N_EDGES;
    while (lo < hi) { int mid = (lo + hi) >> 1; if (row[mid] <  node) lo = mid + 1; else hi = mid; }
    const int start = lo;
    hi = N_EDGES;
    while (lo < hi) { int mid = (lo + hi) >> 1; if (row[mid] <= node) lo = mid + 1; else hi = mid; }
    const int end = lo;

    float4 acc0 = make_float4(0.f, 0.f, 0.f, 0.f);
    float4 acc1 = make_float4(0.f, 0.f, 0.f, 0.f);
    float4 acc2 = make_float4(0.f, 0.f, 0.f, 0.f);
    float4 acc3 = make_float4(0.f, 0.f, 0.f, 0.f);

    int e = start;
    for (; e + 4 <= end; e += 4) {
        const int c0 = col[e], c1 = col[e+1], c2 = col[e+2], c3 = col[e+3];
        float4 v0 = ((const float4*)(g_xsparse + (size_t)c0 * IN_FEATS))[lane];
        float4 v1 = ((const float4*)(g_xsparse + (size_t)c1 * IN_FEATS))[lane];
        float4 v2 = ((const float4*)(g_xsparse + (size_t)c2 * IN_FEATS))[lane];
        float4 v3 = ((const float4*)(g_xsparse + (size_t)c3 * IN_FEATS))[lane];
        acc0.x += v0.x; acc0.y += v0.y; acc0.z += v0.z; acc0.w += v0.w;
        acc1.x += v1.x; acc1.y += v1.y; acc1.z += v1.z; acc1.w += v1.w;
        acc2.x += v2.x; acc2.y += v2.y; acc2.z += v2.z; acc2.w += v2.w;
        acc3.x += v3.x; acc3.y += v3.y; acc3.z += v3.z; acc3.w += v3.w;
    }
    for (; e < end; e++) {
        const int c0 = col[e];
        float4 v0 = ((const float4*)(g_xsparse + (size_t)c0 * IN_FEATS))[lane];
        acc0.x += v0.x; acc0.y += v0.y; acc0.z += v0.z; acc0.w += v0.w;
    }
    acc0.x += acc1.x + acc2.x + acc3.x;
    acc0.y += acc1.y + acc2.y + acc3.y;
    acc0.z += acc1.z + acc2.z + acc3.z;
    acc0.w += acc1.w + acc2.w + acc3.w;

    const float inv = 1.0f / degrees[node];
    acc0.x *= inv; acc0.y *= inv; acc0.z *= inv; acc0.w *= inv;

    ((float4*)(g_agg + (size_t)node * IN_FEATS))[lane] = acc0;
}

// ---------------------------------------------------------------------------
// K3: tensor-core GEMM (tf32 mma.sync, fp32 accumulate).
//   out[N,256] = [feat|agg] @ [W_self;W_neigh] + b
// 128x128x16 block tile, 8 warps (2M x 4N), 64x32 warp tile, 4x4 m16n8k8.
// Double-buffered smem + register prefetch of next global tile.
// ---------------------------------------------------------------------------
#define BM 128
#define BN 128
#define BK 16
#define AS_STRIDE (BM + 4)
#define BS_STRIDE (BN + 4)
#define NUM_KSTEPS ((2 * IN_FEATS) / BK)   // 16

__device__ __forceinline__ uint32_t f2tf32(float f) {
    uint32_t r;
    asm("cvt.rna.tf32.f32 %0, %1;" : "=r"(r) : "f"(f));
    return r;
}

__device__ __forceinline__ void mma_tf32(float c[4],
    uint32_t a0, uint32_t a1, uint32_t a2, uint32_t a3,
    uint32_t b0, uint32_t b1)
{
    asm volatile(
        "mma.sync.aligned.m16n8k8.row.col.f32.tf32.tf32.f32 "
        "{%0,%1,%2,%3}, {%4,%5,%6,%7}, {%8,%9}, {%0,%1,%2,%3};"
        : "+f"(c[0]), "+f"(c[1]), "+f"(c[2]), "+f"(c[3])
        : "r"(a0), "r"(a1), "r"(a2), "r"(a3), "r"(b0), "r"(b1));
}

__global__ __launch_bounds__(256, 2) void gemm_tf32_kernel(
    const float* __restrict__ feat, const float* __restrict__ W_neigh,
    const float* __restrict__ W_self, const float* __restrict__ bias,
    float* __restrict__ out)
{
    __shared__ uint32_t As[2][BK][AS_STRIDE];   // As[buf][k][m], tf32 bits
    __shared__ uint32_t Bs[2][BK][BS_STRIDE];   // Bs[buf][k][n], tf32 bits

    const int t    = threadIdx.x;
    const int lane = t & 31;
    const int warp = t >> 5;
    const int g    = lane >> 2;      // 0..7
    const int tg   = lane & 3;       // 0..3
    const int warp_m = warp >> 2;    // 0..1  -> M offset *64
    const int warp_n = warp & 3;     // 0..3  -> N offset *32
    const int rowBase = blockIdx.y * BM;
    const int colBase = blockIdx.x * BN;

    float c[4][4][4];
    #pragma unroll
    for (int mt = 0; mt < 4; mt++)
        #pragma unroll
        for (int nt = 0; nt < 4; nt++)
            #pragma unroll
            for (int i = 0; i < 4; i++) c[mt][nt][i] = 0.f;

    // per-thread global load coordinates (2 float4 each for A and B tile)
    const int aIdx0 = t,      aIdx1 = t + 256;          // 0..511
    const int ar0 = aIdx0 >> 2, ac0 = (aIdx0 & 3) * 4;  // row 0..127, k 0/4/8/12
    const int ar1 = aIdx1 >> 2, ac1 = (aIdx1 & 3) * 4;
    const int br0 = aIdx0 >> 5, bc0 = (aIdx0 & 31) * 4; // k 0..15, col 0..124
    const int br1 = aIdx1 >> 5, bc1 = (aIdx1 & 31) * 4;

    float4 ra0, ra1, rb0, rb1;

    // ---- fetch tile kt into registers ----
    auto fetch = [&](int kt) {
        const int kbase = kt * BK;
        const float* __restrict__ Asrc = (kbase < IN_FEATS) ? feat   : g_agg;
        const float* __restrict__ Bsrc = (kbase < IN_FEATS) ? W_self : W_neigh;
        const int ko = kbase & (IN_FEATS - 1);
        const int gr0 = rowBase + ar0;
        const int gr1 = rowBase + ar1;
        ra0 = (gr0 < N_NODES) ? *(const float4*)(Asrc + (size_t)gr0 * IN_FEATS + ko + ac0)
                              : make_float4(0.f,0.f,0.f,0.f);
        ra1 = (gr1 < N_NODES) ? *(const float4*)(Asrc + (size_t)gr1 * IN_FEATS + ko + ac1)
                              : make_float4(0.f,0.f,0.f,0.f);
        rb0 = *(const float4*)(Bsrc + (size_t)(ko + br0) * OUT_FEATS + colBase + bc0);
        rb1 = *(const float4*)(Bsrc + (size_t)(ko + br1) * OUT_FEATS + colBase + bc1);
    };

    // ---- store registers to smem buffer (transpose A, convert tf32) ----
    auto stage = [&](int buf) {
        As[buf][ac0 + 0][ar0] = f2tf32(ra0.x);
        As[buf][ac0 + 1][ar0] = f2tf32(ra0.y);
        As[buf][ac0 + 2][ar0] = f2tf32(ra0.z);
        As[buf][ac0 + 3][ar0] = f2tf32(ra0.w);
        As[buf][ac1 + 0][ar1] = f2tf32(ra1.x);
        As[buf][ac1 + 1][ar1] = f2tf32(ra1.y);
        As[buf][ac1 + 2][ar1] = f2tf32(ra1.z);
        As[buf][ac1 + 3][ar1] = f2tf32(ra1.w);
        Bs[buf][br0][bc0 + 0] = f2tf32(rb0.x);
        Bs[buf][br0][bc0 + 1] = f2tf32(rb0.y);
        Bs[buf][br0][bc0 + 2] = f2tf32(rb0.z);
        Bs[buf][br0][bc0 + 3] = f2tf32(rb0.w);
        Bs[buf][br1][bc1 + 0] = f2tf32(rb1.x);
        Bs[buf][br1][bc1 + 1] = f2tf32(rb1.y);
        Bs[buf][br1][bc1 + 2] = f2tf32(rb1.z);
        Bs[buf][br1][bc1 + 3] = f2tf32(rb1.w);
    };

    fetch(0);
    stage(0);
    __syncthreads();

    #pragma unroll 1
    for (int kt = 0; kt < NUM_KSTEPS; kt++) {
        const int buf = kt & 1;
        if (kt + 1 < NUM_KSTEPS) fetch(kt + 1);

        #pragma unroll
        for (int k8 = 0; k8 < BK; k8 += 8) {
            uint32_t a[4][4], b[4][2];
            #pragma unroll
            for (int mt = 0; mt < 4; mt++) {
                const int m = warp_m * 64 + mt * 16 + g;
                a[mt][0] = As[buf][k8 + tg    ][m];
                a[mt][1] = As[buf][k8 + tg    ][m + 8];
                a[mt][2] = As[buf][k8 + tg + 4][m];
                a[mt][3] = As[buf][k8 + tg + 4][m + 8];
            }
            #pragma unroll
            for (int nt = 0; nt < 4; nt++) {
                const int n = warp_n * 32 + nt * 8 + g;
                b[nt][0] = Bs[buf][k8 + tg    ][n];
                b[nt][1] = Bs[buf][k8 + tg + 4][n];
            }
            #pragma unroll
            for (int mt = 0; mt < 4; mt++)
                #pragma unroll
                for (int nt = 0; nt < 4; nt++)
                    mma_tf32(c[mt][nt], a[mt][0], a[mt][1], a[mt][2], a[mt][3],
                             b[nt][0], b[nt][1]);
        }

        if (kt + 1 < NUM_KSTEPS) {
            stage((kt + 1) & 1);
            __syncthreads();
        }
    }

    // ---- epilogue: bias + store ----
    #pragma unroll
    for (int nt = 0; nt < 4; nt++) {
        const int cb = colBase + warp_n * 32 + nt * 8 + 2 * tg;
        const float2 bv = *(const float2*)(bias + cb);
        #pragma unroll
        for (int mt = 0; mt < 4; mt++) {
            const int r0 = rowBase + warp_m * 64 + mt * 16 + g;
            const int r1 = r0 + 8;
            if (r0 < N_NODES) {
                float2 v0 = make_float2(c[mt][nt][0] + bv.x, c[mt][nt][1] + bv.y);
                *(float2*)(out + (size_t)r0 * OUT_FEATS + cb) = v0;
            }
            if (r1 < N_NODES) {
                float2 v1 = make_float2(c[mt][nt][2] + bv.x, c[mt][nt][3] + bv.y);
                *(float2*)(out + (size_t)r1 * OUT_FEATS + cb) = v1;
            }
        }
    }
}

// ---------------------------------------------------------------------------
extern "C" void kernel_launch(void* const* d_in, const int* in_sizes, int n_in,
                              void* d_out, int out_size)
{
    const float* feat     = (const float*)d_in[0];
    const float* topk_val = (const float*)d_in[1];
    const int*   topk_idx = (const int*)  d_in[2];
    const int*   row      = (const int*)  d_in[3];
    const int*   col      = (const int*)  d_in[4];
    const float* degrees  = (const float*)d_in[5];
    const float* W_neigh  = (const float*)d_in[6];
    const float* W_self   = (const float*)d_in[7];
    const float* b_self   = (const float*)d_in[8];
    float*       out      = (float*)d_out;

    const int nblocks = (N_NODES + 7) / 8;
    scatter_kernel<<<nblocks, 256>>>(topk_val, topk_idx);
    spmm_kernel<<<nblocks, 256>>>(row, col, degrees);

    dim3 grid(OUT_FEATS / BN, (N_NODES + BM - 1) / BM);
    gemm_tf32_kernel<<<grid, 256>>>(feat, W_neigh, W_self, b_self, out);
}

// round 10
// speedup vs baseline: 1.0073x; 1.0073x over previous
#include <cuda_runtime.h>
#include <stdint.h>

#define N_NODES   100000
#define N_EDGES   1600000
#define IN_FEATS  128
#define OUT_FEATS 256
#define K_TOP     32

// Scratch (no cudaMalloc allowed)
__device__ float g_xsparse[(size_t)N_NODES * IN_FEATS];   // 51.2 MB
__device__ float g_agg[(size_t)N_NODES * IN_FEATS];       // 51.2 MB

// ---------------------------------------------------------------------------
// K1: scatter top-k -> dense x_sparse[N,128]. atomicAdd (indices may repeat).
// ---------------------------------------------------------------------------
__global__ __launch_bounds__(256) void scatter_kernel(
    const float* __restrict__ vals, const int* __restrict__ idx)
{
    __shared__ float s[8][IN_FEATS];
    const int warp = threadIdx.x >> 5;
    const int lane = threadIdx.x & 31;
    const int node = blockIdx.x * 8 + warp;
    if (node >= N_NODES) return;

    ((float4*)s[warp])[lane] = make_float4(0.f, 0.f, 0.f, 0.f);
    __syncwarp();

    const float v = vals[(size_t)node * K_TOP + lane];
    const int   i = idx [(size_t)node * K_TOP + lane];
    atomicAdd(&s[warp][i], v);
    __syncwarp();

    ((float4*)(g_xsparse + (size_t)node * IN_FEATS))[lane] = ((float4*)s[warp])[lane];
}

// ---------------------------------------------------------------------------
// K2: SpMM (mean agg). Warp per node, binary search on sorted row[], 4-deep
// unrolled float4 gathers from L2-resident x_sparse for MLP.
// ---------------------------------------------------------------------------
__global__ __launch_bounds__(256) void spmm_kernel(
    const int* __restrict__ row, const int* __restrict__ col,
    const float* __restrict__ degrees)
{
    const int warp = threadIdx.x >> 5;
    const int lane = threadIdx.x & 31;
    const int node = blockIdx.x * 8 + warp;
    if (node >= N_NODES) return;

    int lo = 0, hi = N_EDGES;
    while (lo < hi) { int mid = (lo + hi) >> 1; if (row[mid] <  node) lo = mid + 1; else hi = mid; }
    const int start = lo;
    hi = N_EDGES;
    while (lo < hi) { int mid = (lo + hi) >> 1; if (row[mid] <= node) lo = mid + 1; else hi = mid; }
    const int end = lo;

    float4 acc0 = make_float4(0.f, 0.f, 0.f, 0.f);
    float4 acc1 = make_float4(0.f, 0.f, 0.f, 0.f);
    float4 acc2 = make_float4(0.f, 0.f, 0.f, 0.f);
    float4 acc3 = make_float4(0.f, 0.f, 0.f, 0.f);

    int e = start;
    for (; e + 4 <= end; e += 4) {
        const int c0 = col[e], c1 = col[e+1], c2 = col[e+2], c3 = col[e+3];
        float4 v0 = ((const float4*)(g_xsparse + (size_t)c0 * IN_FEATS))[lane];
        float4 v1 = ((const float4*)(g_xsparse + (size_t)c1 * IN_FEATS))[lane];
        float4 v2 = ((const float4*)(g_xsparse + (size_t)c2 * IN_FEATS))[lane];
        float4 v3 = ((const float4*)(g_xsparse + (size_t)c3 * IN_FEATS))[lane];
        acc0.x += v0.x; acc0.y += v0.y; acc0.z += v0.z; acc0.w += v0.w;
        acc1.x += v1.x; acc1.y += v1.y; acc1.z += v1.z; acc1.w += v1.w;
        acc2.x += v2.x; acc2.y += v2.y; acc2.z += v2.z; acc2.w += v2.w;
        acc3.x += v3.x; acc3.y += v3.y; acc3.z += v3.z; acc3.w += v3.w;
    }
    for (; e < end; e++) {
        const int c0 = col[e];
        float4 v0 = ((const float4*)(g_xsparse + (size_t)c0 * IN_FEATS))[lane];
        acc0.x += v0.x; acc0.y += v0.y; acc0.z += v0.z; acc0.w += v0.w;
    }
    acc0.x += acc1.x + acc2.x + acc3.x;
    acc0.y += acc1.y + acc2.y + acc3.y;
    acc0.z += acc1.z + acc2.z + acc3.z;
    acc0.w += acc1.w + acc2.w + acc3.w;

    const float inv = 1.0f / degrees[node];
    acc0.x *= inv; acc0.y *= inv; acc0.z *= inv; acc0.w *= inv;

    ((float4*)(g_agg + (size_t)node * IN_FEATS))[lane] = acc0;
}

// ---------------------------------------------------------------------------
// K3: tensor-core GEMM (tf32 mma.sync, fp32 accumulate).
//   out[N,256] = [feat|agg] @ [W_self;W_neigh] + b
// 128x128x16 block tile, 8 warps (2M x 4N), 64x32 warp tile, 4x4 m16n8k8.
// Double-buffered smem + register prefetch of next global tile.
// ---------------------------------------------------------------------------
#define BM 128
#define BN 128
#define BK 16
#define AS_STRIDE (BM + 4)
#define BS_STRIDE (BN + 4)
#define NUM_KSTEPS ((2 * IN_FEATS) / BK)   // 16

__device__ __forceinline__ uint32_t f2tf32(float f) {
    uint32_t r;
    asm("cvt.rna.tf32.f32 %0, %1;" : "=r"(r) : "f"(f));
    return r;
}

__device__ __forceinline__ void mma_tf32(float c[4],
    uint32_t a0, uint32_t a1, uint32_t a2, uint32_t a3,
    uint32_t b0, uint32_t b1)
{
    asm volatile(
        "mma.sync.aligned.m16n8k8.row.col.f32.tf32.tf32.f32 "
        "{%0,%1,%2,%3}, {%4,%5,%6,%7}, {%8,%9}, {%0,%1,%2,%3};"
        : "+f"(c[0]), "+f"(c[1]), "+f"(c[2]), "+f"(c[3])
        : "r"(a0), "r"(a1), "r"(a2), "r"(a3), "r"(b0), "r"(b1));
}

__global__ __launch_bounds__(256, 2) void gemm_tf32_kernel(
    const float* __restrict__ feat, const float* __restrict__ W_neigh,
    const float* __restrict__ W_self, const float* __restrict__ bias,
    float* __restrict__ out)
{
    __shared__ uint32_t As[2][BK][AS_STRIDE];   // As[buf][k][m], tf32 bits
    __shared__ uint32_t Bs[2][BK][BS_STRIDE];   // Bs[buf][k][n], tf32 bits

    const int t    = threadIdx.x;
    const int lane = t & 31;
    const int warp = t >> 5;
    const int g    = lane >> 2;      // 0..7
    const int tg   = lane & 3;       // 0..3
    const int warp_m = warp >> 2;    // 0..1  -> M offset *64
    const int warp_n = warp & 3;     // 0..3  -> N offset *32
    const int rowBase = blockIdx.y * BM;
    const int colBase = blockIdx.x * BN;

    float c[4][4][4];
    #pragma unroll
    for (int mt = 0; mt < 4; mt++)
        #pragma unroll
        for (int nt = 0; nt < 4; nt++)
            #pragma unroll
            for (int i = 0; i < 4; i++) c[mt][nt][i] = 0.f;

    // per-thread global load coordinates (2 float4 each for A and B tile)
    const int aIdx0 = t,      aIdx1 = t + 256;          // 0..511
    const int ar0 = aIdx0 >> 2, ac0 = (aIdx0 & 3) * 4;  // row 0..127, k 0/4/8/12
    const int ar1 = aIdx1 >> 2, ac1 = (aIdx1 & 3) * 4;
    const int br0 = aIdx0 >> 5, bc0 = (aIdx0 & 31) * 4; // k 0..15, col 0..124
    const int br1 = aIdx1 >> 5, bc1 = (aIdx1 & 31) * 4;

    float4 ra0, ra1, rb0, rb1;

    // ---- fetch tile kt into registers ----
    auto fetch = [&](int kt) {
        const int kbase = kt * BK;
        const float* __restrict__ Asrc = (kbase < IN_FEATS) ? feat   : g_agg;
        const float* __restrict__ Bsrc = (kbase < IN_FEATS) ? W_self : W_neigh;
        const int ko = kbase & (IN_FEATS - 1);
        const int gr0 = rowBase + ar0;
        const int gr1 = rowBase + ar1;
        ra0 = (gr0 < N_NODES) ? *(const float4*)(Asrc + (size_t)gr0 * IN_FEATS + ko + ac0)
                              : make_float4(0.f,0.f,0.f,0.f);
        ra1 = (gr1 < N_NODES) ? *(const float4*)(Asrc + (size_t)gr1 * IN_FEATS + ko + ac1)
                              : make_float4(0.f,0.f,0.f,0.f);
        rb0 = *(const float4*)(Bsrc + (size_t)(ko + br0) * OUT_FEATS + colBase + bc0);
        rb1 = *(const float4*)(Bsrc + (size_t)(ko + br1) * OUT_FEATS + colBase + bc1);
    };

    // ---- store registers to smem buffer (transpose A, convert tf32) ----
    auto stage = [&](int buf) {
        As[buf][ac0 + 0][ar0] = f2tf32(ra0.x);
        As[buf][ac0 + 1][ar0] = f2tf32(ra0.y);
        As[buf][ac0 + 2][ar0] = f2tf32(ra0.z);
        As[buf][ac0 + 3][ar0] = f2tf32(ra0.w);
        As[buf][ac1 + 0][ar1] = f2tf32(ra1.x);
        As[buf][ac1 + 1][ar1] = f2tf32(ra1.y);
        As[buf][ac1 + 2][ar1] = f2tf32(ra1.z);
        As[buf][ac1 + 3][ar1] = f2tf32(ra1.w);
        Bs[buf][br0][bc0 + 0] = f2tf32(rb0.x);
        Bs[buf][br0][bc0 + 1] = f2tf32(rb0.y);
        Bs[buf][br0][bc0 + 2] = f2tf32(rb0.z);
        Bs[buf][br0][bc0 + 3] = f2tf32(rb0.w);
        Bs[buf][br1][bc1 + 0] = f2tf32(rb1.x);
        Bs[buf][br1][bc1 + 1] = f2tf32(rb1.y);
        Bs[buf][br1][bc1 + 2] = f2tf32(rb1.z);
        Bs[buf][br1][bc1 + 3] = f2tf32(rb1.w);
    };

    fetch(0);
    stage(0);
    __syncthreads();

    #pragma unroll 1
    for (int kt = 0; kt < NUM_KSTEPS; kt++) {
        const int buf = kt & 1;
        if (kt + 1 < NUM_KSTEPS) fetch(kt + 1);

        #pragma unroll
        for (int k8 = 0; k8 < BK; k8 += 8) {
            uint32_t a[4][4], b[4][2];
            #pragma unroll
            for (int mt = 0; mt < 4; mt++) {
                const int m = warp_m * 64 + mt * 16 + g;
                a[mt][0] = As[buf][k8 + tg    ][m];
                a[mt][1] = As[buf][k8 + tg    ][m + 8];
                a[mt][2] = As[buf][k8 + tg + 4][m];
                a[mt][3] = As[buf][k8 + tg + 4][m + 8];
            }
            #pragma unroll
            for (int nt = 0; nt < 4; nt++) {
                const int n = warp_n * 32 + nt * 8 + g;
                b[nt][0] = Bs[buf][k8 + tg    ][n];
                b[nt][1] = Bs[buf][k8 + tg + 4][n];
            }
            #pragma unroll
            for (int mt = 0; mt < 4; mt++)
                #pragma unroll
                for (int nt = 0; nt < 4; nt++)
                    mma_tf32(c[mt][nt], a[mt][0], a[mt][1], a[mt][2], a[mt][3],
                             b[nt][0], b[nt][1]);
        }

        if (kt + 1 < NUM_KSTEPS) {
            stage((kt + 1) & 1);
            __syncthreads();
        }
    }

    // ---- epilogue: bias + store ----
    #pragma unroll
    for (int nt = 0; nt < 4; nt++) {
        const int cb = colBase + warp_n * 32 + nt * 8 + 2 * tg;
        const float2 bv = *(const float2*)(bias + cb);
        #pragma unroll
        for (int mt = 0; mt < 4; mt++) {
            const int r0 = rowBase + warp_m * 64 + mt * 16 + g;
            const int r1 = r0 + 8;
            if (r0 < N_NODES) {
                float2 v0 = make_float2(c[mt][nt][0] + bv.x, c[mt][nt][1] + bv.y);
                *(float2*)(out + (size_t)r0 * OUT_FEATS + cb) = v0;
            }
            if (r1 < N_NODES) {
                float2 v1 = make_float2(c[mt][nt][2] + bv.x, c[mt][nt][3] + bv.y);
                *(float2*)(out + (size_t)r1 * OUT_FEATS + cb) = v1;
            }
        }
    }
}

// ---------------------------------------------------------------------------
extern "C" void kernel_launch(void* const* d_in, const int* in_sizes, int n_in,
                              void* d_out, int out_size)
{
    const float* feat     = (const float*)d_in[0];
    const float* topk_val = (const float*)d_in[1];
    const int*   topk_idx = (const int*)  d_in[2];
    const int*   row      = (const int*)  d_in[3];
    const int*   col      = (const int*)  d_in[4];
    const float* degrees  = (const float*)d_in[5];
    const float* W_neigh  = (const float*)d_in[6];
    const float* W_self   = (const float*)d_in[7];
    const float* b_self   = (const float*)d_in[8];
    float*       out      = (float*)d_out;

    const int nblocks = (N_NODES + 7) / 8;
    scatter_kernel<<<nblocks, 256>>>(topk_val, topk_idx);
    spmm_kernel<<<nblocks, 256>>>(row, col, degrees);

    dim3 grid(OUT_FEATS / BN, (N_NODES + BM - 1) / BM);
    gemm_tf32_kernel<<<grid, 256>>>(feat, W_neigh, W_self, b_self, out);
}